// round 7
// baseline (speedup 1.0000x reference)
#include <cuda_runtime.h>
#include <cuda_fp16.h>
#include <math.h>
#include <stdint.h>

// Problem constants
#define NN 8192
#define FF 256
#define DD 128
#define CC 512          // NH*DD feature columns (GEMM N = 512)

// aggr GEMM tiling: CTA 128x128, 4 warps (2m x 2n), warp 64x64
// swizzled smem rows: 128B (64 halves), chunk c' = c ^ (r&7)
#define KST 64                    // fp16 K elements per stage
#define NST 3                     // pipeline stages
#define A_BYTES (128 * 128)       // 16384
#define B_BYTES (128 * 128)       // 16384
#define B2_BYTES (16 * 128)       // 2048
#define STAGE (A_BYTES + B_BYTES + B2_BYTES)  // 34816
#define SMEMB (NST * STAGE)       // 104448  -> 2 CTAs/SM

// Scratch (device globals; zero-initialized at module load)
__device__ __half g_htT[(size_t)CC * NN];   // 8 MB  lrelu(h@W) transposed [c][j]
__device__ float  g_tgt[4 * NN];
__device__ __half g_wT[16 * NN];            // rows 0..3 = w_h[j]; rows 4..15 zero
__device__ __half g_Ah[(size_t)NN * NN];    // 128 MB adjacency as fp16
__device__ __half g_VT[(size_t)CC * NN];    // 8 MB  V^T = w * htT
__device__ float  g_O[(size_t)NN * CC];     // 16 MB numerators
__device__ float  g_den[NN * 4];            // denominators

// ---------------------------------------------------------------------------
// helpers (sm_80-compatible PTX only)
// ---------------------------------------------------------------------------
__device__ __forceinline__ uint32_t smem_u32(const void* p) {
    uint32_t a;
    asm("{ .reg .u64 t; cvta.to.shared.u64 t, %1; cvt.u32.u64 %0, t; }" : "=r"(a) : "l"(p));
    return a;
}
static __device__ __forceinline__ void cp16(uint32_t dst, const void* src) {
    asm volatile("cp.async.cg.shared.global [%0], [%1], 16;" :: "r"(dst), "l"(src));
}
static __device__ __forceinline__ void cp_commit() {
    asm volatile("cp.async.commit_group;" ::: "memory");
}
__device__ __forceinline__ void ldsm4(uint32_t& r0, uint32_t& r1, uint32_t& r2,
                                      uint32_t& r3, uint32_t addr) {
    asm volatile("ldmatrix.sync.aligned.m8n8.x4.shared.b16 {%0,%1,%2,%3}, [%4];"
                 : "=r"(r0), "=r"(r1), "=r"(r2), "=r"(r3) : "r"(addr));
}
__device__ __forceinline__ void mma16816(float* d, const uint32_t* a,
                                         uint32_t b0, uint32_t b1) {
    asm volatile("mma.sync.aligned.m16n8k16.row.col.f32.f16.f16.f32 "
                 "{%0,%1,%2,%3}, {%4,%5,%6,%7}, {%8,%9}, {%0,%1,%2,%3};"
                 : "+f"(d[0]), "+f"(d[1]), "+f"(d[2]), "+f"(d[3])
                 : "r"(a[0]), "r"(a[1]), "r"(a[2]), "r"(a[3]), "r"(b0), "r"(b1));
}
// swizzled byte offset within an operand tile: row r (0..127), 16B chunk c (0..7)
__device__ __forceinline__ uint32_t swz(int r, int c) {
    return (uint32_t)(r * 128 + ((c ^ (r & 7)) << 4));
}

// ---------------------------------------------------------------------------
// Kernel 0 (fused): CTAs 0..255 -> proj HMMA + LeakyReLU + tgt + htT store
//                   CTAs 256..  -> adjacency int32 -> fp16
// ---------------------------------------------------------------------------
__global__ __launch_bounds__(256) void k_fused(const float* __restrict__ hp,
                                               const float* __restrict__ W,
                                               const float* __restrict__ av,
                                               const int* __restrict__ Adj) {
    __shared__ __align__(16) char sm[34816 + 1024];
    const int bid = blockIdx.x;

    if (bid >= 256) {
        const size_t base = ((size_t)(bid - 256) * 256 + threadIdx.x) * 8;
        const size_t stride = (size_t)2048 * 256 * 8;
#pragma unroll
        for (int it = 0; it < 16; it++) {
            size_t idx = base + (size_t)it * stride;
            int4 a = *reinterpret_cast<const int4*>(Adj + idx);
            int4 b = *reinterpret_cast<const int4*>(Adj + idx + 4);
            __half2 h2[4];
            h2[0] = __halves2half2(__int2half_rn(a.x), __int2half_rn(a.y));
            h2[1] = __halves2half2(__int2half_rn(a.z), __int2half_rn(a.w));
            h2[2] = __halves2half2(__int2half_rn(b.x), __int2half_rn(b.y));
            h2[3] = __halves2half2(__int2half_rn(b.z), __int2half_rn(b.w));
            *reinterpret_cast<uint4*>(g_Ah + idx) = *reinterpret_cast<uint4*>(h2);
        }
        return;
    }

    const uint32_t sb = smem_u32(sm);
    float* tgtp = reinterpret_cast<float*>(sm + 34816);
    const int tid = threadIdx.x;
    const int lane = tid & 31;
    const int wid = tid >> 5;
    const int wm = wid & 3;
    const int wn = wid >> 2;
    const int m0 = (bid >> 2) * 128;
    const int hh = bid & 3;
    const int n0 = hh * 128;

    float acc[2][8][4];
#pragma unroll
    for (int f = 0; f < 2; f++)
#pragma unroll
        for (int g = 0; g < 8; g++)
#pragma unroll
            for (int e = 0; e < 4; e++) acc[f][g][e] = 0.f;

    const int lr = lane & 15;
    const int lk = (lane >> 4) * 8;

    for (int k0 = 0; k0 < FF; k0 += 32) {
#pragma unroll
        for (int i = 0; i < 4; i++) {
            int idx = i * 256 + tid;
            int r = idx >> 3, c = idx & 7;
            float4 v = *reinterpret_cast<const float4*>(hp + (size_t)(m0 + r) * FF + k0 + c * 4);
            __half2 lo = __floats2half2_rn(v.x, v.y);
            __half2 hi = __floats2half2_rn(v.z, v.w);
            uint2 u = { *reinterpret_cast<uint32_t*>(&lo), *reinterpret_cast<uint32_t*>(&hi) };
            *reinterpret_cast<uint2*>(sm + r * 80 + c * 8) = u;
        }
#pragma unroll
        for (int i = 0; i < 4; i++) {
            int idx = i * 256 + tid;
            int kk = idx >> 5, n4 = idx & 31;
            float4 v = *reinterpret_cast<const float4*>(W + (size_t)(k0 + kk) * CC + n0 + n4 * 4);
            *reinterpret_cast<__half*>(sm + 10240 + (n4 * 4 + 0) * 80 + kk * 2) = __float2half(v.x);
            *reinterpret_cast<__half*>(sm + 10240 + (n4 * 4 + 1) * 80 + kk * 2) = __float2half(v.y);
            *reinterpret_cast<__half*>(sm + 10240 + (n4 * 4 + 2) * 80 + kk * 2) = __float2half(v.z);
            *reinterpret_cast<__half*>(sm + 10240 + (n4 * 4 + 3) * 80 + kk * 2) = __float2half(v.w);
        }
        __syncthreads();
#pragma unroll
        for (int kk = 0; kk < 2; kk++) {
            const uint32_t koff = (kk * 16 + lk) * 2;
            uint32_t af[2][4], bf[4][4];
#pragma unroll
            for (int f = 0; f < 2; f++)
                ldsm4(af[f][0], af[f][1], af[f][2], af[f][3],
                      sb + (wm * 32 + f * 16 + lr) * 80 + koff);
#pragma unroll
            for (int g = 0; g < 4; g++)
                ldsm4(bf[g][0], bf[g][1], bf[g][2], bf[g][3],
                      sb + 10240 + (wn * 64 + g * 16 + lr) * 80 + koff);
#pragma unroll
            for (int f = 0; f < 2; f++)
#pragma unroll
                for (int g = 0; g < 4; g++) {
                    mma16816(acc[f][g * 2 + 0], af[f], bf[g][0], bf[g][2]);
                    mma16816(acc[f][g * 2 + 1], af[f], bf[g][1], bf[g][3]);
                }
        }
        __syncthreads();
    }

#pragma unroll
    for (int f = 0; f < 2; f++)
#pragma unroll
        for (int g = 0; g < 8; g++)
#pragma unroll
            for (int e = 0; e < 4; e++) {
                float x = acc[f][g][e];
                acc[f][g][e] = (x >= 0.f) ? x : 0.1f * x;
            }

    float av0[8], av1[8];
#pragma unroll
    for (int g = 0; g < 8; g++) {
        int col = wn * 64 + g * 8 + (lane & 3) * 2;
        av0[g] = av[hh * 256 + 128 + col];
        av1[g] = av[hh * 256 + 128 + col + 1];
    }
#pragma unroll
    for (int f = 0; f < 2; f++) {
        float s0 = 0.f, s1 = 0.f;
#pragma unroll
        for (int g = 0; g < 8; g++) {
            s0 += acc[f][g][0] * av0[g] + acc[f][g][1] * av1[g];
            s1 += acc[f][g][2] * av0[g] + acc[f][g][3] * av1[g];
        }
        s0 += __shfl_xor_sync(0xFFFFFFFFu, s0, 1);
        s0 += __shfl_xor_sync(0xFFFFFFFFu, s0, 2);
        s1 += __shfl_xor_sync(0xFFFFFFFFu, s1, 1);
        s1 += __shfl_xor_sync(0xFFFFFFFFu, s1, 2);
        if ((lane & 3) == 0) {
            int row = wm * 32 + f * 16 + (lane >> 2);
            tgtp[wn * 128 + row] = s0;
            tgtp[wn * 128 + row + 8] = s1;
        }
    }

#pragma unroll
    for (int f = 0; f < 2; f++) {
        int row = wm * 32 + f * 16 + (lane >> 2);
#pragma unroll
        for (int g = 0; g < 8; g++) {
            int c0 = wn * 64 + g * 8 + (lane & 3) * 2;
            *reinterpret_cast<__half*>(sm + c0 * 272 + row * 2)       = __float2half(acc[f][g][0]);
            *reinterpret_cast<__half*>(sm + (c0 + 1) * 272 + row * 2) = __float2half(acc[f][g][1]);
            *reinterpret_cast<__half*>(sm + c0 * 272 + (row + 8) * 2)       = __float2half(acc[f][g][2]);
            *reinterpret_cast<__half*>(sm + (c0 + 1) * 272 + (row + 8) * 2) = __float2half(acc[f][g][3]);
        }
    }
    __syncthreads();

    if (tid < 128)
        g_tgt[hh * NN + m0 + tid] = tgtp[tid] + tgtp[128 + tid];

#pragma unroll
    for (int i = 0; i < 8; i++) {
        int idx = i * 256 + tid;
        int c = idx >> 4, q = idx & 15;
        *reinterpret_cast<uint4*>(g_htT + (size_t)(hh * 128 + c) * NN + m0 + q * 8) =
            *reinterpret_cast<uint4*>(sm + c * 272 + q * 16);
    }
}

// ---------------------------------------------------------------------------
// Kernel 1: per-head max + w = exp(tgt - max)
// ---------------------------------------------------------------------------
__global__ __launch_bounds__(256) void k_maxw() {
    __shared__ float red[256];
    const int hh = blockIdx.x;
    const int tid = threadIdx.x;
    float m = -1e30f;
    for (int j = tid; j < NN; j += 256) m = fmaxf(m, g_tgt[hh * NN + j]);
    red[tid] = m;
    __syncthreads();
#pragma unroll
    for (int s = 128; s; s >>= 1) {
        if (tid < s) red[tid] = fmaxf(red[tid], red[tid + s]);
        __syncthreads();
    }
    const float mh = red[0];
    for (int j = tid; j < NN; j += 256)
        g_wT[hh * NN + j] = __float2half(expf(g_tgt[hh * NN + j] - mh));
}

// ---------------------------------------------------------------------------
// Kernel 2: VT[n][j] = htT[n][j] * wT[n>>7][j]
// ---------------------------------------------------------------------------
__global__ __launch_bounds__(256) void k_buildVT() {
    size_t idx = ((size_t)blockIdx.x * 256 + threadIdx.x) * 8;
    int n = (int)(idx >> 13);
    int j = (int)(idx & 8191);
    uint4 hv = *reinterpret_cast<const uint4*>(g_htT + idx);
    const __half2* wp = reinterpret_cast<const __half2*>(g_wT + (size_t)(n >> 7) * NN + j);
    __half2* hp2 = reinterpret_cast<__half2*>(&hv);
#pragma unroll
    for (int e = 0; e < 4; e++) hp2[e] = __hmul2(hp2[e], wp[e]);
    *reinterpret_cast<uint4*>(g_VT + idx) = hv;
}

// ---------------------------------------------------------------------------
// Kernel 3: O = A @ V. CTA 128x128, 4 warps (2m x 2n), warp 64x64.
// Swizzled smem, KST 64, NST 3, 2 CTAs/SM. grid (4 n, 64 m). den fused.
// ---------------------------------------------------------------------------
__device__ __forceinline__ void load_stage(int t, uint32_t sb, int m0, int n0, int tid) {
    const int k0 = t * KST;
    const uint32_t base = sb + (t % NST) * STAGE;
    // A: 128 rows x 8 chunks = 1024 (8/thread)
#pragma unroll
    for (int i = 0; i < 8; i++) {
        int idx = i * 128 + tid;
        int r = idx >> 3, c = idx & 7;
        cp16(base + swz(r, c), g_Ah + (size_t)(m0 + r) * NN + k0 + c * 8);
    }
    // B: 128 rows x 8 chunks
#pragma unroll
    for (int i = 0; i < 8; i++) {
        int idx = i * 128 + tid;
        int r = idx >> 3, c = idx & 7;
        cp16(base + A_BYTES + swz(r, c), g_VT + (size_t)(n0 + r) * NN + k0 + c * 8);
    }
    // B2: 16 rows x 8 chunks
    {
        int r = tid >> 3, c = tid & 7;
        cp16(base + A_BYTES + B_BYTES + swz(r, c), g_wT + (size_t)r * NN + k0 + c * 8);
    }
}

__global__ __launch_bounds__(128, 2) void k_aggr_mma() {
    extern __shared__ __align__(128) char smem[];
    const uint32_t sb = smem_u32(smem);
    const int tid = threadIdx.x;
    const int lane = tid & 31;
    const int wid = tid >> 5;
    const int wm = wid & 1;        // 2 m positions x 64 rows
    const int wn = wid >> 1;       // 2 n positions x 64 cols
    const int n0 = blockIdx.x * 128;
    const int m0 = blockIdx.y * 128;
    const bool do_den = (blockIdx.x == 0) && (wn == 0);

    float acc[4][8][4];
#pragma unroll
    for (int f = 0; f < 4; f++)
#pragma unroll
        for (int g = 0; g < 8; g++)
#pragma unroll
            for (int e = 0; e < 4; e++) acc[f][g][e] = 0.f;
    float dacc[4][4];
#pragma unroll
    for (int f = 0; f < 4; f++)
#pragma unroll
        for (int e = 0; e < 4; e++) dacc[f][e] = 0.f;

#pragma unroll
    for (int s = 0; s < NST; s++) {
        load_stage(s, sb, m0, n0, tid);
        cp_commit();
    }

    const int lr = lane & 15;
    const int lcol = lane >> 4;     // 0/1: which 16B k-col within kk

    const int S = NN / KST;  // 128
    for (int s = 0; s < S; s++) {
        asm volatile("cp.async.wait_group %0;" :: "n"(NST - 1) : "memory");
        __syncthreads();
        const uint32_t st = sb + (s % NST) * STAGE;
#pragma unroll
        for (int kk = 0; kk < 4; kk++) {
            const int c16 = kk * 2 + lcol;   // 16B chunk index 0..7
            uint32_t af[4][4], bf[4][4];
#pragma unroll
            for (int f = 0; f < 4; f++) {
                int r = wm * 64 + f * 16 + lr;
                ldsm4(af[f][0], af[f][1], af[f][2], af[f][3], st + swz(r, c16));
            }
#pragma unroll
            for (int g = 0; g < 4; g++) {
                int r = wn * 64 + g * 16 + lr;
                ldsm4(bf[g][0], bf[g][1], bf[g][2], bf[g][3],
                      st + A_BYTES + swz(r, c16));
            }
#pragma unroll
            for (int f = 0; f < 4; f++)
#pragma unroll
                for (int g = 0; g < 4; g++) {
                    mma16816(acc[f][g * 2 + 0], af[f], bf[g][0], bf[g][2]);
                    mma16816(acc[f][g * 2 + 1], af[f], bf[g][1], bf[g][3]);
                }
            if (do_den) {
                uint32_t bw[4];
                ldsm4(bw[0], bw[1], bw[2], bw[3],
                      st + A_BYTES + B_BYTES + swz(lr, c16));
#pragma unroll
                for (int f = 0; f < 4; f++)
                    mma16816(dacc[f], af[f], bw[0], bw[2]);
            }
        }
        __syncthreads();
        if (s + NST < S) {
            load_stage(s + NST, sb, m0, n0, tid);
            cp_commit();
        }
    }

    // epilogue
#pragma unroll
    for (int f = 0; f < 4; f++) {
        const int row = m0 + wm * 64 + f * 16 + (lane >> 2);
#pragma unroll
        for (int g = 0; g < 8; g++) {
            const int col = n0 + wn * 64 + g * 8 + (lane & 3) * 2;
            float2 v0 = {acc[f][g][0], acc[f][g][1]};
            float2 v1 = {acc[f][g][2], acc[f][g][3]};
            *reinterpret_cast<float2*>(g_O + (size_t)row * CC + col) = v0;
            *reinterpret_cast<float2*>(g_O + (size_t)(row + 8) * CC + col) = v1;
        }
    }
    if (do_den) {
        const int c2 = (lane & 3) * 2;
        if (c2 < 4) {
#pragma unroll
            for (int f = 0; f < 4; f++) {
                const int row = m0 + wm * 64 + f * 16 + (lane >> 2);
                g_den[row * 4 + c2 + 0] = dacc[f][0];
                g_den[row * 4 + c2 + 1] = dacc[f][1];
                g_den[(row + 8) * 4 + c2 + 0] = dacc[f][2];
                g_den[(row + 8) * 4 + c2 + 1] = dacc[f][3];
            }
        }
    }
}

// ---------------------------------------------------------------------------
// Kernel 4: out[i][d] = 0.25 * sum_h num[h]/den[h]
// ---------------------------------------------------------------------------
__global__ __launch_bounds__(128) void k_out(float* __restrict__ out) {
    const int i = blockIdx.x;
    const int d = threadIdx.x;
    __shared__ float inv[4];
    if (d < 4) inv[d] = 1.0f / g_den[i * 4 + d];
    __syncthreads();
    float s = 0.f;
#pragma unroll
    for (int h = 0; h < 4; h++) s += g_O[(size_t)i * CC + h * DD + d] * inv[h];
    out[(size_t)i * DD + d] = 0.25f * s;
}

// ---------------------------------------------------------------------------
extern "C" void kernel_launch(void* const* d_in, const int* in_sizes, int n_in,
                              void* d_out, int out_size) {
    const float* h   = (const float*)d_in[0];
    const int*   adj = (const int*)d_in[1];
    const float* W   = (const float*)d_in[2];
    const float* a   = (const float*)d_in[3];
    float* out = (float*)d_out;

    static int init_done = 0;
    if (!init_done) {
        cudaFuncSetAttribute(k_aggr_mma, cudaFuncAttributeMaxDynamicSharedMemorySize, SMEMB);
        init_done = 1;
    }

    k_fused<<<2304, 256>>>(h, W, a, adj);        // launch 0: proj + conv
    k_maxw<<<4, 256>>>();                        // launch 1
    k_buildVT<<<2048, 256>>>();                  // launch 2
    k_aggr_mma<<<dim3(4, 64), 128, SMEMB>>>();   // launch 3  <- profiled
    k_out<<<8192, 128>>>(out);                   // launch 4
}

// round 8
// speedup vs baseline: 1.4930x; 1.4930x over previous
#include <cuda_runtime.h>
#include <cuda_fp16.h>
#include <math.h>
#include <stdint.h>

// Problem constants
#define NN 8192
#define FF 256
#define DD 128
#define CC 512          // NH*DD feature columns (GEMM N = 512)

// aggr GEMM tiling: CTA 256x128, 8 warps (4m x 2n), warp 64x64
// XOR-swizzled smem rows (128B), 16B chunk c' = c ^ (r&7)
#define KST 64                    // fp16 K elements per stage
#define NST 4                     // pipeline stages
#define A_BYTES (256 * 128)       // 32768
#define B_BYTES (128 * 128)       // 16384
#define B2_BYTES (16 * 128)       // 2048
#define STAGE (A_BYTES + B_BYTES + B2_BYTES)  // 51200
#define SMEMB (NST * STAGE)       // 204800

// Scratch (device globals; zero-initialized at module load)
__device__ __half g_htT[(size_t)CC * NN];   // 8 MB  lrelu(h@W) transposed [c][j]
__device__ float  g_tgt[4 * NN];
__device__ __half g_wT[16 * NN];            // rows 0..3 = w_h[j]; rows 4..15 zero
__device__ __half g_Ah[(size_t)NN * NN];    // 128 MB adjacency as fp16
__device__ __half g_VT[(size_t)CC * NN];    // 8 MB  V^T = w * htT
__device__ float  g_O[(size_t)NN * CC];     // 16 MB numerators
__device__ float  g_den[NN * 4];            // denominators

// ---------------------------------------------------------------------------
// helpers (sm_80-compatible PTX only)
// ---------------------------------------------------------------------------
__device__ __forceinline__ uint32_t smem_u32(const void* p) {
    uint32_t a;
    asm("{ .reg .u64 t; cvta.to.shared.u64 t, %1; cvt.u32.u64 %0, t; }" : "=r"(a) : "l"(p));
    return a;
}
static __device__ __forceinline__ void cp16(uint32_t dst, const void* src) {
    asm volatile("cp.async.cg.shared.global [%0], [%1], 16;" :: "r"(dst), "l"(src));
}
static __device__ __forceinline__ void cp_commit() {
    asm volatile("cp.async.commit_group;" ::: "memory");
}
__device__ __forceinline__ void ldsm4(uint32_t& r0, uint32_t& r1, uint32_t& r2,
                                      uint32_t& r3, uint32_t addr) {
    asm volatile("ldmatrix.sync.aligned.m8n8.x4.shared.b16 {%0,%1,%2,%3}, [%4];"
                 : "=r"(r0), "=r"(r1), "=r"(r2), "=r"(r3) : "r"(addr));
}
__device__ __forceinline__ void mma16816(float* d, const uint32_t* a,
                                         uint32_t b0, uint32_t b1) {
    asm volatile("mma.sync.aligned.m16n8k16.row.col.f32.f16.f16.f32 "
                 "{%0,%1,%2,%3}, {%4,%5,%6,%7}, {%8,%9}, {%0,%1,%2,%3};"
                 : "+f"(d[0]), "+f"(d[1]), "+f"(d[2]), "+f"(d[3])
                 : "r"(a[0]), "r"(a[1]), "r"(a[2]), "r"(a[3]), "r"(b0), "r"(b1));
}
// swizzled byte offset: row r, 16B chunk c (0..7) within a 128B-row tile
__device__ __forceinline__ uint32_t swz(int r, int c) {
    return (uint32_t)(r * 128 + ((c ^ (r & 7)) << 4));
}

// ---------------------------------------------------------------------------
// Kernel 0 (fused): CTAs 0..255 -> proj HMMA + LeakyReLU + tgt + htT store
//                   CTAs 256..  -> adjacency int32 -> fp16
// ---------------------------------------------------------------------------
__global__ __launch_bounds__(256) void k_fused(const float* __restrict__ hp,
                                               const float* __restrict__ W,
                                               const float* __restrict__ av,
                                               const int* __restrict__ Adj) {
    __shared__ __align__(16) char sm[34816 + 1024];
    const int bid = blockIdx.x;

    if (bid >= 256) {
        const size_t base = ((size_t)(bid - 256) * 256 + threadIdx.x) * 8;
        const size_t stride = (size_t)2048 * 256 * 8;
#pragma unroll
        for (int it = 0; it < 16; it++) {
            size_t idx = base + (size_t)it * stride;
            int4 a = *reinterpret_cast<const int4*>(Adj + idx);
            int4 b = *reinterpret_cast<const int4*>(Adj + idx + 4);
            __half2 h2[4];
            h2[0] = __halves2half2(__int2half_rn(a.x), __int2half_rn(a.y));
            h2[1] = __halves2half2(__int2half_rn(a.z), __int2half_rn(a.w));
            h2[2] = __halves2half2(__int2half_rn(b.x), __int2half_rn(b.y));
            h2[3] = __halves2half2(__int2half_rn(b.z), __int2half_rn(b.w));
            *reinterpret_cast<uint4*>(g_Ah + idx) = *reinterpret_cast<uint4*>(h2);
        }
        return;
    }

    const uint32_t sb = smem_u32(sm);
    float* tgtp = reinterpret_cast<float*>(sm + 34816);
    const int tid = threadIdx.x;
    const int lane = tid & 31;
    const int wid = tid >> 5;
    const int wm = wid & 3;
    const int wn = wid >> 2;
    const int m0 = (bid >> 2) * 128;
    const int hh = bid & 3;
    const int n0 = hh * 128;

    float acc[2][8][4];
#pragma unroll
    for (int f = 0; f < 2; f++)
#pragma unroll
        for (int g = 0; g < 8; g++)
#pragma unroll
            for (int e = 0; e < 4; e++) acc[f][g][e] = 0.f;

    const int lr = lane & 15;
    const int lk = (lane >> 4) * 8;

    for (int k0 = 0; k0 < FF; k0 += 32) {
#pragma unroll
        for (int i = 0; i < 4; i++) {
            int idx = i * 256 + tid;
            int r = idx >> 3, c = idx & 7;
            float4 v = *reinterpret_cast<const float4*>(hp + (size_t)(m0 + r) * FF + k0 + c * 4);
            __half2 lo = __floats2half2_rn(v.x, v.y);
            __half2 hi = __floats2half2_rn(v.z, v.w);
            uint2 u = { *reinterpret_cast<uint32_t*>(&lo), *reinterpret_cast<uint32_t*>(&hi) };
            *reinterpret_cast<uint2*>(sm + r * 80 + c * 8) = u;
        }
#pragma unroll
        for (int i = 0; i < 4; i++) {
            int idx = i * 256 + tid;
            int kk = idx >> 5, n4 = idx & 31;
            float4 v = *reinterpret_cast<const float4*>(W + (size_t)(k0 + kk) * CC + n0 + n4 * 4);
            *reinterpret_cast<__half*>(sm + 10240 + (n4 * 4 + 0) * 80 + kk * 2) = __float2half(v.x);
            *reinterpret_cast<__half*>(sm + 10240 + (n4 * 4 + 1) * 80 + kk * 2) = __float2half(v.y);
            *reinterpret_cast<__half*>(sm + 10240 + (n4 * 4 + 2) * 80 + kk * 2) = __float2half(v.z);
            *reinterpret_cast<__half*>(sm + 10240 + (n4 * 4 + 3) * 80 + kk * 2) = __float2half(v.w);
        }
        __syncthreads();
#pragma unroll
        for (int kk = 0; kk < 2; kk++) {
            const uint32_t koff = (kk * 16 + lk) * 2;
            uint32_t af[2][4], bf[4][4];
#pragma unroll
            for (int f = 0; f < 2; f++)
                ldsm4(af[f][0], af[f][1], af[f][2], af[f][3],
                      sb + (wm * 32 + f * 16 + lr) * 80 + koff);
#pragma unroll
            for (int g = 0; g < 4; g++)
                ldsm4(bf[g][0], bf[g][1], bf[g][2], bf[g][3],
                      sb + 10240 + (wn * 64 + g * 16 + lr) * 80 + koff);
#pragma unroll
            for (int f = 0; f < 2; f++)
#pragma unroll
                for (int g = 0; g < 4; g++) {
                    mma16816(acc[f][g * 2 + 0], af[f], bf[g][0], bf[g][2]);
                    mma16816(acc[f][g * 2 + 1], af[f], bf[g][1], bf[g][3]);
                }
        }
        __syncthreads();
    }

#pragma unroll
    for (int f = 0; f < 2; f++)
#pragma unroll
        for (int g = 0; g < 8; g++)
#pragma unroll
            for (int e = 0; e < 4; e++) {
                float x = acc[f][g][e];
                acc[f][g][e] = (x >= 0.f) ? x : 0.1f * x;
            }

    float av0[8], av1[8];
#pragma unroll
    for (int g = 0; g < 8; g++) {
        int col = wn * 64 + g * 8 + (lane & 3) * 2;
        av0[g] = av[hh * 256 + 128 + col];
        av1[g] = av[hh * 256 + 128 + col + 1];
    }
#pragma unroll
    for (int f = 0; f < 2; f++) {
        float s0 = 0.f, s1 = 0.f;
#pragma unroll
        for (int g = 0; g < 8; g++) {
            s0 += acc[f][g][0] * av0[g] + acc[f][g][1] * av1[g];
            s1 += acc[f][g][2] * av0[g] + acc[f][g][3] * av1[g];
        }
        s0 += __shfl_xor_sync(0xFFFFFFFFu, s0, 1);
        s0 += __shfl_xor_sync(0xFFFFFFFFu, s0, 2);
        s1 += __shfl_xor_sync(0xFFFFFFFFu, s1, 1);
        s1 += __shfl_xor_sync(0xFFFFFFFFu, s1, 2);
        if ((lane & 3) == 0) {
            int row = wm * 32 + f * 16 + (lane >> 2);
            tgtp[wn * 128 + row] = s0;
            tgtp[wn * 128 + row + 8] = s1;
        }
    }

#pragma unroll
    for (int f = 0; f < 2; f++) {
        int row = wm * 32 + f * 16 + (lane >> 2);
#pragma unroll
        for (int g = 0; g < 8; g++) {
            int c0 = wn * 64 + g * 8 + (lane & 3) * 2;
            *reinterpret_cast<__half*>(sm + c0 * 272 + row * 2)       = __float2half(acc[f][g][0]);
            *reinterpret_cast<__half*>(sm + (c0 + 1) * 272 + row * 2) = __float2half(acc[f][g][1]);
            *reinterpret_cast<__half*>(sm + c0 * 272 + (row + 8) * 2)       = __float2half(acc[f][g][2]);
            *reinterpret_cast<__half*>(sm + (c0 + 1) * 272 + (row + 8) * 2) = __float2half(acc[f][g][3]);
        }
    }
    __syncthreads();

    if (tid < 128)
        g_tgt[hh * NN + m0 + tid] = tgtp[tid] + tgtp[128 + tid];

#pragma unroll
    for (int i = 0; i < 8; i++) {
        int idx = i * 256 + tid;
        int c = idx >> 4, q = idx & 15;
        *reinterpret_cast<uint4*>(g_htT + (size_t)(hh * 128 + c) * NN + m0 + q * 8) =
            *reinterpret_cast<uint4*>(sm + c * 272 + q * 16);
    }
}

// ---------------------------------------------------------------------------
// Kernel 1: per-head max + w = exp(tgt - max)
// ---------------------------------------------------------------------------
__global__ __launch_bounds__(256) void k_maxw() {
    __shared__ float red[256];
    const int hh = blockIdx.x;
    const int tid = threadIdx.x;
    float m = -1e30f;
    for (int j = tid; j < NN; j += 256) m = fmaxf(m, g_tgt[hh * NN + j]);
    red[tid] = m;
    __syncthreads();
#pragma unroll
    for (int s = 128; s; s >>= 1) {
        if (tid < s) red[tid] = fmaxf(red[tid], red[tid + s]);
        __syncthreads();
    }
    const float mh = red[0];
    for (int j = tid; j < NN; j += 256)
        g_wT[hh * NN + j] = __float2half(expf(g_tgt[hh * NN + j] - mh));
}

// ---------------------------------------------------------------------------
// Kernel 2: VT[n][j] = htT[n][j] * wT[n>>7][j]
// ---------------------------------------------------------------------------
__global__ __launch_bounds__(256) void k_buildVT() {
    size_t idx = ((size_t)blockIdx.x * 256 + threadIdx.x) * 8;
    int n = (int)(idx >> 13);
    int j = (int)(idx & 8191);
    uint4 hv = *reinterpret_cast<const uint4*>(g_htT + idx);
    const __half2* wp = reinterpret_cast<const __half2*>(g_wT + (size_t)(n >> 7) * NN + j);
    __half2* hp2 = reinterpret_cast<__half2*>(&hv);
#pragma unroll
    for (int e = 0; e < 4; e++) hp2[e] = __hmul2(hp2[e], wp[e]);
    *reinterpret_cast<uint4*>(g_VT + idx) = hv;
}

// ---------------------------------------------------------------------------
// Kernel 3: O = A @ V. CTA 256x128, 8 warps (4m x 2n), warp 64x64.
// Swizzled compact smem, KST 64, NST 4, single sync per stage.
// grid (4 n fast, 32 m) = 128 CTAs (one/SM). den fused on n-tile 0.
// ---------------------------------------------------------------------------
__device__ __forceinline__ void load_stage(int t, uint32_t sb, int m0, int n0, int tid) {
    const int k0 = t * KST;
    const uint32_t base = sb + (t & (NST - 1)) * STAGE;
    // A: 256 rows x 8 chunks = 2048 -> 8/thread
#pragma unroll
    for (int i = 0; i < 8; i++) {
        int idx = i * 256 + tid;
        int r = idx >> 3, c = idx & 7;
        cp16(base + swz(r, c), g_Ah + (size_t)(m0 + r) * NN + k0 + c * 8);
    }
    // B: 128 rows x 8 chunks = 1024 -> 4/thread
#pragma unroll
    for (int i = 0; i < 4; i++) {
        int idx = i * 256 + tid;
        int r = idx >> 3, c = idx & 7;
        cp16(base + A_BYTES + swz(r, c), g_VT + (size_t)(n0 + r) * NN + k0 + c * 8);
    }
    // B2: 16 rows x 8 chunks = 128
    if (tid < 128) {
        int r = tid >> 3, c = tid & 7;
        cp16(base + A_BYTES + B_BYTES + swz(r, c), g_wT + (size_t)r * NN + k0 + c * 8);
    }
}

__global__ __launch_bounds__(256, 1) void k_aggr_mma() {
    extern __shared__ __align__(128) char smem[];
    const uint32_t sb = smem_u32(smem);
    const int tid = threadIdx.x;
    const int lane = tid & 31;
    const int wid = tid >> 5;
    const int wm = wid & 3;
    const int wn = wid >> 2;
    const int n0 = blockIdx.x * 128;
    const int m0 = blockIdx.y * 256;
    const bool do_den = (blockIdx.x == 0) && (wn == 0);

    float acc[4][8][4];
#pragma unroll
    for (int f = 0; f < 4; f++)
#pragma unroll
        for (int g = 0; g < 8; g++)
#pragma unroll
            for (int e = 0; e < 4; e++) acc[f][g][e] = 0.f;
    float dacc[4][4];
#pragma unroll
    for (int f = 0; f < 4; f++)
#pragma unroll
        for (int e = 0; e < 4; e++) dacc[f][e] = 0.f;

    // prologue: stages 0..2
#pragma unroll
    for (int s = 0; s < NST - 1; s++) {
        load_stage(s, sb, m0, n0, tid);
        cp_commit();
    }

    const int lr = lane & 15;
    const int lcol = lane >> 4;

    const int S = NN / KST;  // 128
    for (int s = 0; s < S; s++) {
        asm volatile("cp.async.wait_group %0;" :: "n"(NST - 2) : "memory");
        __syncthreads();
        const uint32_t st = sb + (s & (NST - 1)) * STAGE;
#pragma unroll
        for (int kk = 0; kk < 4; kk++) {
            const int c16 = kk * 2 + lcol;
            uint32_t af[4][4], bf[4][4];
#pragma unroll
            for (int f = 0; f < 4; f++) {
                int r = wm * 64 + f * 16 + lr;
                ldsm4(af[f][0], af[f][1], af[f][2], af[f][3], st + swz(r, c16));
            }
#pragma unroll
            for (int g = 0; g < 4; g++) {
                int r = wn * 64 + g * 16 + lr;
                ldsm4(bf[g][0], bf[g][1], bf[g][2], bf[g][3],
                      st + A_BYTES + swz(r, c16));
            }
#pragma unroll
            for (int f = 0; f < 4; f++)
#pragma unroll
                for (int g = 0; g < 4; g++) {
                    mma16816(acc[f][g * 2 + 0], af[f], bf[g][0], bf[g][2]);
                    mma16816(acc[f][g * 2 + 1], af[f], bf[g][1], bf[g][3]);
                }
            if (do_den) {
                uint32_t bw[4];
                ldsm4(bw[0], bw[1], bw[2], bw[3],
                      st + A_BYTES + B_BYTES + swz(lr, c16));
#pragma unroll
                for (int f = 0; f < 4; f++)
                    mma16816(dacc[f], af[f], bw[0], bw[2]);
            }
        }
        // load stage s+NST-1 into buffer (s-1)%NST (consumed last iter; safe post-sync)
        const int t2 = s + NST - 1;
        if (t2 < S) load_stage(t2, sb, m0, n0, tid);
        cp_commit();
    }

    // epilogue
#pragma unroll
    for (int f = 0; f < 4; f++) {
        const int row = m0 + wm * 64 + f * 16 + (lane >> 2);
#pragma unroll
        for (int g = 0; g < 8; g++) {
            const int col = n0 + wn * 64 + g * 8 + (lane & 3) * 2;
            float2 v0 = {acc[f][g][0], acc[f][g][1]};
            float2 v1 = {acc[f][g][2], acc[f][g][3]};
            *reinterpret_cast<float2*>(g_O + (size_t)row * CC + col) = v0;
            *reinterpret_cast<float2*>(g_O + (size_t)(row + 8) * CC + col) = v1;
        }
    }
    if (do_den) {
        const int c2 = (lane & 3) * 2;
        if (c2 < 4) {
#pragma unroll
            for (int f = 0; f < 4; f++) {
                const int row = m0 + wm * 64 + f * 16 + (lane >> 2);
                g_den[row * 4 + c2 + 0] = dacc[f][0];
                g_den[row * 4 + c2 + 1] = dacc[f][1];
                g_den[(row + 8) * 4 + c2 + 0] = dacc[f][2];
                g_den[(row + 8) * 4 + c2 + 1] = dacc[f][3];
            }
        }
    }
}

// ---------------------------------------------------------------------------
// Kernel 4: out[i][d] = 0.25 * sum_h num[h]/den[h]
// ---------------------------------------------------------------------------
__global__ __launch_bounds__(128) void k_out(float* __restrict__ out) {
    const int i = blockIdx.x;
    const int d = threadIdx.x;
    __shared__ float inv[4];
    if (d < 4) inv[d] = 1.0f / g_den[i * 4 + d];
    __syncthreads();
    float s = 0.f;
#pragma unroll
    for (int h = 0; h < 4; h++) s += g_O[(size_t)i * CC + h * DD + d] * inv[h];
    out[(size_t)i * DD + d] = 0.25f * s;
}

// ---------------------------------------------------------------------------
extern "C" void kernel_launch(void* const* d_in, const int* in_sizes, int n_in,
                              void* d_out, int out_size) {
    const float* h   = (const float*)d_in[0];
    const int*   adj = (const int*)d_in[1];
    const float* W   = (const float*)d_in[2];
    const float* a   = (const float*)d_in[3];
    float* out = (float*)d_out;

    static int init_done = 0;
    if (!init_done) {
        cudaFuncSetAttribute(k_aggr_mma, cudaFuncAttributeMaxDynamicSharedMemorySize, SMEMB);
        init_done = 1;
    }

    k_fused<<<2304, 256>>>(h, W, a, adj);        // launch 0: proj + conv
    k_maxw<<<4, 256>>>();                        // launch 1
    k_buildVT<<<2048, 256>>>();                  // launch 2
    k_aggr_mma<<<dim3(4, 32), 256, SMEMB>>>();   // launch 3  <- profiled
    k_out<<<8192, 128>>>(out);                   // launch 4
}